// round 1
// baseline (speedup 1.0000x reference)
#include <cuda_runtime.h>
#include <cuda_bf16.h>
#include <math.h>

// ---------------------------------------------------------------------------
// UnifiedAttentionAggregator — gated-attention MIL
//   N=524288 instances, NF=256 feats, L=128, C=1, B=4096 bags
// Inputs (metadata order):
//   0 feats[N*256] f32, 1 split_sizes[B] (int64 or int32), 2 W_ins[256],
//   3 b_ins[1], 4 W_V[256*128], 5 b_V[128], 6 W_U[256*128], 7 b_U[128],
//   8 w_att[128], 9 b_att[1]
// Output: bag_pred[4096] then inst_pred[524288]  (528384 f32)
// ---------------------------------------------------------------------------

#define N_INST 524288
#define NF     256
#define L_DIM  128
#define NBAGS  4096

__device__ float g_scores[N_INST];
__device__ int   g_offs[NBAGS + 1];

// ---- packed f32x2 helpers (sm_103a) ---------------------------------------
__device__ __forceinline__ unsigned long long dup2(float x) {
    unsigned long long r;
    asm("mov.b64 %0, {%1, %1};" : "=l"(r) : "r"(__float_as_uint(x)));
    return r;
}
__device__ __forceinline__ unsigned long long pk2(float x, float y) {
    unsigned long long r;
    asm("mov.b64 %0, {%1, %2};" : "=l"(r) : "r"(__float_as_uint(x)), "r"(__float_as_uint(y)));
    return r;
}
__device__ __forceinline__ void fma2(unsigned long long& d,
                                     unsigned long long a,
                                     unsigned long long b) {
    asm("fma.rn.f32x2 %0, %1, %2, %0;" : "+l"(d) : "l"(a), "l"(b));
}
__device__ __forceinline__ float2 up2(unsigned long long v) {
    unsigned int lo, hi;
    asm("mov.b64 {%0, %1}, %2;" : "=r"(lo), "=r"(hi) : "l"(v));
    float2 f;
    f.x = __uint_as_float(lo);
    f.y = __uint_as_float(hi);
    return f;
}

// ---------------------------------------------------------------------------
// Kernel 0: prefix-sum of split_sizes -> g_offs. One block of 1024 threads,
// 4 elements each. Detects int64 vs int32 storage: sizes are all >= 64, so
// for little-endian int64 the odd int32 words are zero.
// ---------------------------------------------------------------------------
__global__ void scan_kernel(const int* __restrict__ sz32) {
    __shared__ int ssum[1024];
    const int t = threadIdx.x;
    const int stride = (sz32[1] == 0) ? 2 : 1;  // int64 -> read every other word

    int v[4];
    int s = 0;
#pragma unroll
    for (int j = 0; j < 4; ++j) {
        v[j] = sz32[(4 * t + j) * stride];
        s += v[j];
    }
    ssum[t] = s;
    __syncthreads();

    // inclusive Hillis–Steele scan over 1024 partials
    for (int off = 1; off < 1024; off <<= 1) {
        int x = (t >= off) ? ssum[t - off] : 0;
        __syncthreads();
        ssum[t] += x;
        __syncthreads();
    }

    int run = ssum[t] - s;  // exclusive prefix
#pragma unroll
    for (int j = 0; j < 4; ++j) {
        g_offs[4 * t + j] = run;
        run += v[j];
    }
    if (t == 1023) g_offs[NBAGS] = run;
}

// ---------------------------------------------------------------------------
// Kernel 1: fused GEMM + gate epilogue.
//   C[N,256] = feats @ [W_V | W_U], plus inst = feats @ W_ins (extra column),
//   score[i] = b_att + sum_l tanh(C[i,l]+b_V[l])*sigmoid(C[i,l+128]+b_U[l])*w_att[l]
// Tiling: BM=64 rows, BN=256 (full), BK=16, 256 threads, 8x8 micro-tile per
// thread packed into 32 f32x2 accumulators (column pairs).
// ---------------------------------------------------------------------------
__global__ __launch_bounds__(256) void gemm_kernel(
    const float* __restrict__ feats,
    const float* __restrict__ W_V, const float* __restrict__ b_V,
    const float* __restrict__ W_U, const float* __restrict__ b_U,
    const float* __restrict__ W_ins, const float* __restrict__ b_ins,
    const float* __restrict__ w_att, const float* __restrict__ b_att,
    float* __restrict__ out_inst)
{
    // smem union: GEMM buffers (A 16x68, B 16x256, ins 16) overlaid by the
    // post-loop U-exchange buffer (64x128).
    __shared__ __align__(16) unsigned char sm[33024];
    float (*A_s)[68]   = (float(*)[68])sm;                     //  4352 B
    float (*B_s)[256]  = (float(*)[256])(sm + 4352);           // 16384 B
    float*  ins_s      = (float*)(sm + 4352 + 16384);          //    64 B
    float (*U_s)[128]  = (float(*)[128])sm;                    // 32768 B (after loop)

    const int tid  = threadIdx.x;
    const int tx   = tid & 31;        // 32 column groups of 8
    const int ty   = tid >> 5;        // 8 row groups of 8
    const int row0 = blockIdx.x * 64;
    const int rowA = ty * 8;
    const int colB = tx * 8;
    const int r_ins = tx & 7;

    unsigned long long acc[8][4];
#pragma unroll
    for (int r = 0; r < 8; ++r)
#pragma unroll
        for (int j = 0; j < 4; ++j) acc[r][j] = 0ULL;
    float ins_acc = 0.f;

    const int lrow = tid >> 2;   // 0..63 : A-tile row this thread loads
    const int lkq  = tid & 3;    // which float4 of the 16-wide k slice

    for (int kt = 0; kt < NF / 16; ++kt) {
        const int k0 = kt * 16;
        __syncthreads();

        // --- load A tile [64 rows x 16 k], store k-major (transposed) ---
        {
            float4 fa = *(const float4*)&feats[(row0 + lrow) * NF + k0 + lkq * 4];
            A_s[lkq * 4 + 0][lrow] = fa.x;
            A_s[lkq * 4 + 1][lrow] = fa.y;
            A_s[lkq * 4 + 2][lrow] = fa.z;
            A_s[lkq * 4 + 3][lrow] = fa.w;
        }
        // --- load B tile [16 k x 256 cols] = [W_V | W_U] ---
#pragma unroll
        for (int i = 0; i < 4; ++i) {
            const int chunk = tid + 256 * i;
            const int kk = chunk >> 6;
            const int c4 = (chunk & 63) << 2;
            const float* src = (c4 < L_DIM)
                ? &W_V[(k0 + kk) * L_DIM + c4]
                : &W_U[(k0 + kk) * L_DIM + (c4 - L_DIM)];
            *(float4*)&B_s[kk][c4] = *(const float4*)src;
        }
        if (tid < 16) ins_s[tid] = W_ins[k0 + tid];
        __syncthreads();

        // --- compute ---
#pragma unroll
        for (int k = 0; k < 16; ++k) {
            float4 a0 = *(const float4*)&A_s[k][rowA];
            float4 a1 = *(const float4*)&A_s[k][rowA + 4];
            float4 b0 = *(const float4*)&B_s[k][colB];
            float4 b1 = *(const float4*)&B_s[k][colB + 4];

            unsigned long long A2[8];
            A2[0] = dup2(a0.x); A2[1] = dup2(a0.y);
            A2[2] = dup2(a0.z); A2[3] = dup2(a0.w);
            A2[4] = dup2(a1.x); A2[5] = dup2(a1.y);
            A2[6] = dup2(a1.z); A2[7] = dup2(a1.w);
            unsigned long long Bp[4];
            Bp[0] = pk2(b0.x, b0.y); Bp[1] = pk2(b0.z, b0.w);
            Bp[2] = pk2(b1.x, b1.y); Bp[3] = pk2(b1.z, b1.w);

            ins_acc = fmaf(A_s[k][rowA + r_ins], ins_s[k], ins_acc);

#pragma unroll
            for (int r = 0; r < 8; ++r)
#pragma unroll
                for (int j = 0; j < 4; ++j) fma2(acc[r][j], A2[r], Bp[j]);
        }
    }

    // ---- epilogue ----------------------------------------------------------
    __syncthreads();  // everyone done with A_s/B_s before U_s overlay

    if (tx >= 16) {
        const int lb = colB - L_DIM;  // this thread's U columns l = lb..lb+7
#pragma unroll
        for (int r = 0; r < 8; ++r)
#pragma unroll
            for (int jp = 0; jp < 4; ++jp) {
                float2 p = up2(acc[r][jp]);
                U_s[rowA + r][lb + 2 * jp]     = p.x;
                U_s[rowA + r][lb + 2 * jp + 1] = p.y;
            }
    }
    __syncwarp();  // V-half lanes (tx<16) read U written by same-warp lanes

    float s[8];
#pragma unroll
    for (int r = 0; r < 8; ++r) s[r] = 0.f;

    if (tx < 16) {
#pragma unroll
        for (int r = 0; r < 8; ++r) {
            float part = 0.f;
#pragma unroll
            for (int jp = 0; jp < 4; ++jp) {
                float2 p = up2(acc[r][jp]);
                const int l = colB + 2 * jp;
                float u0 = U_s[rowA + r][l]     + b_U[l];
                float u1 = U_s[rowA + r][l + 1] + b_U[l + 1];
                float v0 = tanhf(p.x + b_V[l]);
                float v1 = tanhf(p.y + b_V[l + 1]);
                part += v0 * (1.f / (1.f + expf(-u0))) * w_att[l];
                part += v1 * (1.f / (1.f + expf(-u1))) * w_att[l + 1];
            }
            s[r] = part;
        }
    }
    // reduce over the 16 V-lanes (xor distances < 16 keep halves separate)
#pragma unroll
    for (int d = 8; d >= 1; d >>= 1)
#pragma unroll
        for (int r = 0; r < 8; ++r)
            s[r] += __shfl_xor_sync(0xffffffffu, s[r], d);

    if (tx == 0) {
        const float ba = b_att[0];
#pragma unroll
        for (int r = 0; r < 8; ++r)
            g_scores[row0 + rowA + r] = s[r] + ba;
    }
    if (tx < 8) {
        out_inst[row0 + rowA + tx] = ins_acc + b_ins[0];
    }
}

// ---------------------------------------------------------------------------
// Kernel 2: per-bag segmented softmax + weighted sum (C=1).
// One 128-thread block per bag.
// ---------------------------------------------------------------------------
__global__ void bag_kernel(const float* __restrict__ inst,
                           float* __restrict__ out_bag)
{
    const int b   = blockIdx.x;
    const int tid = threadIdx.x;
    const int s0  = g_offs[b];
    const int s1  = g_offs[b + 1];

    __shared__ float rm[4], re[4], rp[4];

    float m = -3.4e38f;
    for (int i = s0 + tid; i < s1; i += 128) m = fmaxf(m, g_scores[i]);
#pragma unroll
    for (int d = 16; d >= 1; d >>= 1)
        m = fmaxf(m, __shfl_xor_sync(0xffffffffu, m, d));
    if ((tid & 31) == 0) rm[tid >> 5] = m;
    __syncthreads();
    m = fmaxf(fmaxf(rm[0], rm[1]), fmaxf(rm[2], rm[3]));

    float se = 0.f, sp = 0.f;
    for (int i = s0 + tid; i < s1; i += 128) {
        float e = expf(g_scores[i] - m);
        se += e;
        sp += e * inst[i];
    }
#pragma unroll
    for (int d = 16; d >= 1; d >>= 1) {
        se += __shfl_xor_sync(0xffffffffu, se, d);
        sp += __shfl_xor_sync(0xffffffffu, sp, d);
    }
    if ((tid & 31) == 0) { re[tid >> 5] = se; rp[tid >> 5] = sp; }
    __syncthreads();
    if (tid == 0) {
        float SE = re[0] + re[1] + re[2] + re[3];
        float SP = rp[0] + rp[1] + rp[2] + rp[3];
        out_bag[b] = SP / SE;
    }
}

// ---------------------------------------------------------------------------
extern "C" void kernel_launch(void* const* d_in, const int* in_sizes, int n_in,
                              void* d_out, int out_size)
{
    const float* feats = (const float*)d_in[0];
    const int*   sz32  = (const int*)d_in[1];   // int32 view; scan detects width
    const float* W_ins = (const float*)d_in[2];
    const float* b_ins = (const float*)d_in[3];
    const float* W_V   = (const float*)d_in[4];
    const float* b_V   = (const float*)d_in[5];
    const float* W_U   = (const float*)d_in[6];
    const float* b_U   = (const float*)d_in[7];
    const float* w_att = (const float*)d_in[8];
    const float* b_att = (const float*)d_in[9];

    float* out      = (float*)d_out;
    float* out_bag  = out;            // [4096]
    float* out_inst = out + NBAGS;    // [524288]

    scan_kernel<<<1, 1024>>>(sz32);
    gemm_kernel<<<N_INST / 64, 256>>>(feats, W_V, b_V, W_U, b_U,
                                      W_ins, b_ins, w_att, b_att, out_inst);
    bag_kernel<<<NBAGS, 128>>>(out_inst, out_bag);
}

// round 4
// speedup vs baseline: 3.6844x; 3.6844x over previous
#include <cuda_runtime.h>
#include <cuda_bf16.h>
#include <math.h>
#include <stdint.h>

// ---------------------------------------------------------------------------
// UnifiedAttentionAggregator — bf16-split GEMM on mma.sync (HMMA), sm_103-safe
//   C[N,256] = feats @ [W_V | W_U] via ah*Wh + al*Wh + ah*Wl
// ---------------------------------------------------------------------------

#define N_INST 524288
#define NF     256
#define L_DIM  128
#define NBAGS  4096
#define NTILES (N_INST / 64)

// smem layout (bytes)
#define OFF_WINS 0
#define OFF_BV   1024
#define OFF_BU   1536
#define OFF_WA   2048
#define OFF_AH   2560
#define OFF_AL   (OFF_AH + 64 * 144)       // 11776
#define OFF_BH   (OFF_AL + 64 * 144)       // 20992
#define OFF_BL   (OFF_BH + 64 * 528)       // 54784
#define SM_TOTAL (OFF_BL + 64 * 528)       // 88576
#define OFF_C    2560                      // epilogue overlay, stride 1088 B

__device__ float g_scores[N_INST];
__device__ int   g_offs[NBAGS + 1];
__device__ __align__(16) __nv_bfloat16 g_Wh[NF * 256];  // [k][n]
__device__ __align__(16) __nv_bfloat16 g_Wl[NF * 256];

// ---- helpers --------------------------------------------------------------
__device__ __forceinline__ uint32_t smem_u32(const void* p) {
    uint32_t a;
    asm("{ .reg .u64 t; cvta.to.shared.u64 t, %1; cvt.u32.u64 %0, t; }" : "=r"(a) : "l"(p));
    return a;
}
// pack two f32 -> bf16x2 (lo in low half)
__device__ __forceinline__ uint32_t cvt2(float lo, float hi) {
    uint32_t d;
    asm("cvt.rn.bf16x2.f32 %0, %1, %2;" : "=r"(d) : "f"(hi), "f"(lo));
    return d;
}
__device__ __forceinline__ float bf_lo(uint32_t h) { return __uint_as_float(h << 16); }
__device__ __forceinline__ float bf_hi(uint32_t h) { return __uint_as_float(h & 0xFFFF0000u); }

__device__ __forceinline__ void ldsm4(uint32_t& r0, uint32_t& r1, uint32_t& r2, uint32_t& r3,
                                      uint32_t addr) {
    asm volatile("ldmatrix.sync.aligned.m8n8.x4.shared.b16 {%0,%1,%2,%3}, [%4];"
                 : "=r"(r0), "=r"(r1), "=r"(r2), "=r"(r3) : "r"(addr));
}
__device__ __forceinline__ void ldsm4t(uint32_t& r0, uint32_t& r1, uint32_t& r2, uint32_t& r3,
                                       uint32_t addr) {
    asm volatile("ldmatrix.sync.aligned.m8n8.x4.trans.shared.b16 {%0,%1,%2,%3}, [%4];"
                 : "=r"(r0), "=r"(r1), "=r"(r2), "=r"(r3) : "r"(addr));
}
__device__ __forceinline__ void mma16816(float* c, uint32_t a0, uint32_t a1, uint32_t a2,
                                         uint32_t a3, uint32_t b0, uint32_t b1) {
    asm volatile(
        "mma.sync.aligned.m16n8k16.row.col.f32.bf16.bf16.f32 "
        "{%0,%1,%2,%3},{%4,%5,%6,%7},{%8,%9},{%0,%1,%2,%3};"
        : "+f"(c[0]), "+f"(c[1]), "+f"(c[2]), "+f"(c[3])
        : "r"(a0), "r"(a1), "r"(a2), "r"(a3), "r"(b0), "r"(b1));
}

// ---------------------------------------------------------------------------
// Kernel 0: bag-offset scan + W split into g_Wh/g_Wl ([k][n] bf16)
// ---------------------------------------------------------------------------
__global__ void scan_kernel(const int* __restrict__ sz32,
                            const float* __restrict__ W_V,
                            const float* __restrict__ W_U) {
    __shared__ int ssum[1024];
    const int t = threadIdx.x;
    const int stride = (sz32[1] == 0) ? 2 : 1;  // int64 storage detection

    int v[4];
    int s = 0;
#pragma unroll
    for (int j = 0; j < 4; ++j) {
        v[j] = sz32[(4 * t + j) * stride];
        s += v[j];
    }
    ssum[t] = s;
    __syncthreads();
    for (int off = 1; off < 1024; off <<= 1) {
        int x = (t >= off) ? ssum[t - off] : 0;
        __syncthreads();
        ssum[t] += x;
        __syncthreads();
    }
    int run = ssum[t] - s;
#pragma unroll
    for (int j = 0; j < 4; ++j) {
        g_offs[4 * t + j] = run;
        run += v[j];
    }
    if (t == 1023) g_offs[NBAGS] = run;

    for (int idx = t; idx < 256 * 256; idx += 1024) {
        int k = idx >> 8, n = idx & 255;
        float w = (n < L_DIM) ? W_V[k * L_DIM + n] : W_U[k * L_DIM + (n - L_DIM)];
        __nv_bfloat16 h = __float2bfloat16_rn(w);
        __nv_bfloat16 l = __float2bfloat16_rn(w - __bfloat162float(h));
        g_Wh[idx] = h;
        g_Wl[idx] = l;
    }
}

// ---------------------------------------------------------------------------
// Kernel 1: HMMA GEMM + inst_pred + gated-attention epilogue.
// Block: 256 thr (8 warps 2x4), tile 64x256, K chunks of 64, 2 CTAs/SM.
// ---------------------------------------------------------------------------
__global__ __launch_bounds__(256, 2) void gemm_kernel(
    const float* __restrict__ feats,
    const float* __restrict__ W_ins, const float* __restrict__ b_ins,
    const float* __restrict__ b_V, const float* __restrict__ b_U,
    const float* __restrict__ w_att, const float* __restrict__ b_att,
    float* __restrict__ out_inst)
{
    extern __shared__ __align__(16) unsigned char sm[];
    const int tid  = threadIdx.x;
    const int wid  = tid >> 5;
    const int lane = tid & 31;
    const int wm   = wid & 1;    // M-warp (32 rows)
    const int wn   = wid >> 1;   // N-warp (64 cols)
    const int row0 = blockIdx.x * 64;
    const uint32_t smb = smem_u32(sm);

    // consts
    ((float*)(sm + OFF_WINS))[tid] = W_ins[tid];
    if (tid < L_DIM) {
        ((float*)(sm + OFF_BV))[tid] = b_V[tid];
        ((float*)(sm + OFF_BU))[tid] = b_U[tid];
        ((float*)(sm + OFF_WA))[tid] = w_att[tid];
    }
    const float* Wins_s = (const float*)(sm + OFF_WINS);

    float acc[2][8][4];
#pragma unroll
    for (int mt = 0; mt < 2; ++mt)
#pragma unroll
        for (int nf = 0; nf < 8; ++nf)
#pragma unroll
            for (int j = 0; j < 4; ++j) acc[mt][nf][j] = 0.f;

    const int arow = tid >> 2;
    const int akq  = tid & 3;
    const float* aptr = feats + (size_t)(row0 + arow) * NF + akq * 16;
    float insp = 0.f;

    // ldmatrix per-lane base addresses
    const uint32_t aBase = smb + OFF_AH + (uint32_t)(wm * 32 + (lane & 15)) * 144
                         + (uint32_t)(lane >> 4) * 16;
    const uint32_t bBase = smb + OFF_BH + (uint32_t)(lane & 15) * 528
                         + (uint32_t)(wn * 64 + (lane >> 4) * 8) * 2;
    const uint32_t ASTEP = (uint32_t)(OFF_AL - OFF_AH);
    const uint32_t BSTEP = (uint32_t)(OFF_BL - OFF_BH);

    for (int c = 0; c < 4; ++c) {
        __syncthreads();  // smem free (prev compute done / consts visible)

        // ---- A: load fp32, split to bf16 hi/lo, fold inst_pred ----
        {
            const float* ap = aptr + c * 64;
            unsigned char* dstH = sm + OFF_AH + arow * 144 + akq * 32;
            unsigned char* dstL = sm + OFF_AL + arow * 144 + akq * 32;
#pragma unroll
            for (int q = 0; q < 4; ++q) {
                float4 f = *(const float4*)(ap + q * 4);
                const int kk = c * 64 + akq * 16 + q * 4;
                insp += f.x * Wins_s[kk]     + f.y * Wins_s[kk + 1]
                      + f.z * Wins_s[kk + 2] + f.w * Wins_s[kk + 3];
                uint32_t h0 = cvt2(f.x, f.y);
                uint32_t h1 = cvt2(f.z, f.w);
                uint32_t l0 = cvt2(f.x - bf_lo(h0), f.y - bf_hi(h0));
                uint32_t l1 = cvt2(f.z - bf_lo(h1), f.w - bf_hi(h1));
                *(uint2*)(dstH + q * 8) = make_uint2(h0, h1);
                *(uint2*)(dstL + q * 8) = make_uint2(l0, l1);
            }
        }
        // ---- B: copy 64k x 256n bf16 hi/lo from L2-resident globals ----
        {
#pragma unroll
            for (int i = 0; i < 8; ++i) {
                const int idx = tid + 256 * i;
                const int kk = idx >> 5, q = idx & 31;
                const int srcq = ((c * 64 + kk) << 5) + q;
                *(uint4*)(sm + OFF_BH + kk * 528 + q * 16) = ((const uint4*)g_Wh)[srcq];
                *(uint4*)(sm + OFF_BL + kk * 528 + q * 16) = ((const uint4*)g_Wl)[srcq];
            }
        }
        __syncthreads();

        // ---- compute: 3 split terms per k16 step ----
#pragma unroll
        for (int kt = 0; kt < 4; ++kt) {
            const uint32_t aAddr = aBase + kt * 32;
            const uint32_t bAddr = bBase + kt * 16 * 528;
            uint32_t Ah[2][4], Al[2][4], B[4][4];

            ldsm4(Ah[0][0], Ah[0][1], Ah[0][2], Ah[0][3], aAddr);
            ldsm4(Ah[1][0], Ah[1][1], Ah[1][2], Ah[1][3], aAddr + 16 * 144);
#pragma unroll
            for (int n16 = 0; n16 < 4; ++n16)
                ldsm4t(B[n16][0], B[n16][1], B[n16][2], B[n16][3], bAddr + n16 * 32);
#pragma unroll
            for (int mt = 0; mt < 2; ++mt)
#pragma unroll
                for (int nf = 0; nf < 8; ++nf)
                    mma16816(acc[mt][nf], Ah[mt][0], Ah[mt][1], Ah[mt][2], Ah[mt][3],
                             B[nf >> 1][(nf & 1) * 2], B[nf >> 1][(nf & 1) * 2 + 1]);

            ldsm4(Al[0][0], Al[0][1], Al[0][2], Al[0][3], aAddr + ASTEP);
            ldsm4(Al[1][0], Al[1][1], Al[1][2], Al[1][3], aAddr + ASTEP + 16 * 144);
#pragma unroll
            for (int mt = 0; mt < 2; ++mt)
#pragma unroll
                for (int nf = 0; nf < 8; ++nf)
                    mma16816(acc[mt][nf], Al[mt][0], Al[mt][1], Al[mt][2], Al[mt][3],
                             B[nf >> 1][(nf & 1) * 2], B[nf >> 1][(nf & 1) * 2 + 1]);

#pragma unroll
            for (int n16 = 0; n16 < 4; ++n16)
                ldsm4t(B[n16][0], B[n16][1], B[n16][2], B[n16][3], bAddr + BSTEP + n16 * 32);
#pragma unroll
            for (int mt = 0; mt < 2; ++mt)
#pragma unroll
                for (int nf = 0; nf < 8; ++nf)
                    mma16816(acc[mt][nf], Ah[mt][0], Ah[mt][1], Ah[mt][2], Ah[mt][3],
                             B[nf >> 1][(nf & 1) * 2], B[nf >> 1][(nf & 1) * 2 + 1]);
        }
    }

    // ---- instance predictions ----
    insp += __shfl_xor_sync(0xffffffffu, insp, 1);
    insp += __shfl_xor_sync(0xffffffffu, insp, 2);
    if (akq == 0) out_inst[row0 + arow] = insp + b_ins[0];

    // ---- epilogue: accums -> smem C[64][272], then gated scores ----
    __syncthreads();
    {
        const int rbase = wm * 32 + (lane >> 2);
        const int cbase = wn * 64 + (lane & 3) * 2;
#pragma unroll
        for (int mt = 0; mt < 2; ++mt)
#pragma unroll
            for (int nf = 0; nf < 8; ++nf) {
                float* p0 = (float*)(sm + OFF_C + (rbase + mt * 16) * 1088
                                     + (cbase + nf * 8) * 4);
                p0[0] = acc[mt][nf][0];
                p0[1] = acc[mt][nf][1];
                float* p1 = (float*)(sm + OFF_C + (rbase + mt * 16 + 8) * 1088
                                     + (cbase + nf * 8) * 4);
                p1[0] = acc[mt][nf][2];
                p1[1] = acc[mt][nf][3];
            }
    }
    __syncthreads();
    {
        const float* bV_s = (const float*)(sm + OFF_BV);
        const float* bU_s = (const float*)(sm + OFF_BU);
        const float* wa_s = (const float*)(sm + OFF_WA);
        const unsigned char* crow = sm + OFF_C + arow * 1088;
        float part = 0.f;
#pragma unroll
        for (int jj = 0; jj < 8; ++jj) {
            const int l = jj * 16 + akq * 4;
            float4 v = *(const float4*)(crow + l * 4);
            float4 u = *(const float4*)(crow + (l + L_DIM) * 4);
#pragma unroll
            for (int e = 0; e < 4; ++e) {
                float vv = ((const float*)&v)[e] + bV_s[l + e];
                float uu = ((const float*)&u)[e] + bU_s[l + e];
                float th = 2.f * __fdividef(1.f, 1.f + __expf(-2.f * vv)) - 1.f;
                float sg = __fdividef(1.f, 1.f + __expf(-uu));
                part += th * sg * wa_s[l + e];
            }
        }
        part += __shfl_xor_sync(0xffffffffu, part, 1);
        part += __shfl_xor_sync(0xffffffffu, part, 2);
        if (akq == 0) g_scores[row0 + arow] = part + b_att[0];
    }
}

// ---------------------------------------------------------------------------
// Kernel 2: per-bag segmented softmax + weighted sum (C=1).
// ---------------------------------------------------------------------------
__global__ void bag_kernel(const float* __restrict__ inst,
                           float* __restrict__ out_bag)
{
    const int b   = blockIdx.x;
    const int tid = threadIdx.x;
    const int s0  = g_offs[b];
    const int s1  = g_offs[b + 1];

    __shared__ float rm[4], re[4], rp[4];

    float m = -3.4e38f;
    for (int i = s0 + tid; i < s1; i += 128) m = fmaxf(m, g_scores[i]);
#pragma unroll
    for (int d = 16; d >= 1; d >>= 1)
        m = fmaxf(m, __shfl_xor_sync(0xffffffffu, m, d));
    if ((tid & 31) == 0) rm[tid >> 5] = m;
    __syncthreads();
    m = fmaxf(fmaxf(rm[0], rm[1]), fmaxf(rm[2], rm[3]));

    float se = 0.f, sp = 0.f;
    for (int i = s0 + tid; i < s1; i += 128) {
        float e = expf(g_scores[i] - m);
        se += e;
        sp += e * inst[i];
    }
#pragma unroll
    for (int d = 16; d >= 1; d >>= 1) {
        se += __shfl_xor_sync(0xffffffffu, se, d);
        sp += __shfl_xor_sync(0xffffffffu, sp, d);
    }
    if ((tid & 31) == 0) { re[tid >> 5] = se; rp[tid >> 5] = sp; }
    __syncthreads();
    if (tid == 0) {
        out_bag[b] = (rp[0] + rp[1] + rp[2] + rp[3]) /
                     (re[0] + re[1] + re[2] + re[3]);
    }
}

// ---------------------------------------------------------------------------
extern "C" void kernel_launch(void* const* d_in, const int* in_sizes, int n_in,
                              void* d_out, int out_size)
{
    const float* feats = (const float*)d_in[0];
    const int*   sz32  = (const int*)d_in[1];
    const float* W_ins = (const float*)d_in[2];
    const float* b_ins = (const float*)d_in[3];
    const float* W_V   = (const float*)d_in[4];
    const float* b_V   = (const float*)d_in[5];
    const float* W_U   = (const float*)d_in[6];
    const float* b_U   = (const float*)d_in[7];
    const float* w_att = (const float*)d_in[8];
    const float* b_att = (const float*)d_in[9];

    float* out      = (float*)d_out;
    float* out_bag  = out;           // [4096]
    float* out_inst = out + NBAGS;   // [524288]

    cudaFuncSetAttribute(gemm_kernel, cudaFuncAttributeMaxDynamicSharedMemorySize, SM_TOTAL);

    scan_kernel<<<1, 1024>>>(sz32, W_V, W_U);
    gemm_kernel<<<NTILES, 256, SM_TOTAL>>>(feats, W_ins, b_ins, b_V, b_U,
                                           w_att, b_att, out_inst);
    bag_kernel<<<NBAGS, 128>>>(out_inst, out_bag);
}

// round 5
// speedup vs baseline: 4.8781x; 1.3240x over previous
#include <cuda_runtime.h>
#include <cuda_fp16.h>
#include <math.h>
#include <stdint.h>

// ---------------------------------------------------------------------------
// UnifiedAttentionAggregator — fp16 2-term split GEMM on mma.sync (HMMA)
//   C[N,256] = feats @ [W_V | W_U] via (ah + al) * Wh,  ah/al/Wh fp16
// ---------------------------------------------------------------------------

#define N_INST 524288
#define NF     256
#define L_DIM  128
#define NBAGS  4096
#define NTILES (N_INST / 64)

// smem layout (bytes)
#define OFF_WINS 0
#define OFF_BV   1024
#define OFF_BU   1536
#define OFF_WA   2048
#define OFF_AH   2560
#define OFF_AL   (OFF_AH + 64 * 144)       // 11776
#define OFF_BH   (OFF_AL + 64 * 144)       // 20992
#define GEMM_END (OFF_BH + 64 * 528)       // 54784
#define OFF_C    2560                      // epilogue overlay, stride 1088 B
#define SM_TOTAL (OFF_C + 64 * 1088)       // 72192 (overlay is the max)

__device__ float g_scores[N_INST];
__device__ int   g_offs[NBAGS + 1];
__device__ __align__(16) __half g_Wh[NF * 256];  // [k][n] fp16

// ---- helpers --------------------------------------------------------------
__device__ __forceinline__ uint32_t smem_u32(const void* p) {
    uint32_t a;
    asm("{ .reg .u64 t; cvta.to.shared.u64 t, %1; cvt.u32.u64 %0, t; }" : "=r"(a) : "l"(p));
    return a;
}
__device__ __forceinline__ void ldsm4(uint32_t& r0, uint32_t& r1, uint32_t& r2, uint32_t& r3,
                                      uint32_t addr) {
    asm volatile("ldmatrix.sync.aligned.m8n8.x4.shared.b16 {%0,%1,%2,%3}, [%4];"
                 : "=r"(r0), "=r"(r1), "=r"(r2), "=r"(r3) : "r"(addr));
}
__device__ __forceinline__ void ldsm4t(uint32_t& r0, uint32_t& r1, uint32_t& r2, uint32_t& r3,
                                       uint32_t addr) {
    asm volatile("ldmatrix.sync.aligned.m8n8.x4.trans.shared.b16 {%0,%1,%2,%3}, [%4];"
                 : "=r"(r0), "=r"(r1), "=r"(r2), "=r"(r3) : "r"(addr));
}
__device__ __forceinline__ void mma16816(float* c, uint32_t a0, uint32_t a1, uint32_t a2,
                                         uint32_t a3, uint32_t b0, uint32_t b1) {
    asm volatile(
        "mma.sync.aligned.m16n8k16.row.col.f32.f16.f16.f32 "
        "{%0,%1,%2,%3},{%4,%5,%6,%7},{%8,%9},{%0,%1,%2,%3};"
        : "+f"(c[0]), "+f"(c[1]), "+f"(c[2]), "+f"(c[3])
        : "r"(a0), "r"(a1), "r"(a2), "r"(a3), "r"(b0), "r"(b1));
}
__device__ __forceinline__ uint32_t pkh(__half a, __half b) {
    __half2 p = __halves2half2(a, b);
    return *reinterpret_cast<uint32_t*>(&p);
}

// ---------------------------------------------------------------------------
// Kernel 0: bag-offset scan + W -> fp16 [k][n]
// ---------------------------------------------------------------------------
__global__ void scan_kernel(const int* __restrict__ sz32,
                            const float* __restrict__ W_V,
                            const float* __restrict__ W_U) {
    __shared__ int ssum[1024];
    const int t = threadIdx.x;
    const int stride = (sz32[1] == 0) ? 2 : 1;  // int64 storage detection

    int v[4];
    int s = 0;
#pragma unroll
    for (int j = 0; j < 4; ++j) {
        v[j] = sz32[(4 * t + j) * stride];
        s += v[j];
    }
    ssum[t] = s;
    __syncthreads();
    for (int off = 1; off < 1024; off <<= 1) {
        int x = (t >= off) ? ssum[t - off] : 0;
        __syncthreads();
        ssum[t] += x;
        __syncthreads();
    }
    int run = ssum[t] - s;
#pragma unroll
    for (int j = 0; j < 4; ++j) {
        g_offs[4 * t + j] = run;
        run += v[j];
    }
    if (t == 1023) g_offs[NBAGS] = run;

    for (int idx = t; idx < 256 * 256; idx += 1024) {
        int k = idx >> 8, n = idx & 255;
        float w = (n < L_DIM) ? W_V[k * L_DIM + n] : W_U[k * L_DIM + (n - L_DIM)];
        g_Wh[idx] = __float2half_rn(w);
    }
}

// ---------------------------------------------------------------------------
// Kernel 1: HMMA GEMM + inst_pred + gated-attention epilogue.
// Block: 256 thr (8 warps 2x4), tile 64x256, K chunks of 64, 2 CTAs/SM.
// ---------------------------------------------------------------------------
__global__ __launch_bounds__(256, 2) void gemm_kernel(
    const float* __restrict__ feats,
    const float* __restrict__ W_ins, const float* __restrict__ b_ins,
    const float* __restrict__ b_V, const float* __restrict__ b_U,
    const float* __restrict__ w_att, const float* __restrict__ b_att,
    float* __restrict__ out_inst)
{
    extern __shared__ __align__(16) unsigned char sm[];
    const int tid  = threadIdx.x;
    const int wid  = tid >> 5;
    const int lane = tid & 31;
    const int wm   = wid & 1;    // M-warp (32 rows)
    const int wn   = wid >> 1;   // N-warp (64 cols)
    const int row0 = blockIdx.x * 64;
    const uint32_t smb = smem_u32(sm);

    // consts
    ((float*)(sm + OFF_WINS))[tid] = W_ins[tid];
    if (tid < L_DIM) {
        ((float*)(sm + OFF_BV))[tid] = b_V[tid];
        ((float*)(sm + OFF_BU))[tid] = b_U[tid];
        ((float*)(sm + OFF_WA))[tid] = w_att[tid];
    }
    const float* Wins_s = (const float*)(sm + OFF_WINS);

    float acc[2][8][4];
#pragma unroll
    for (int mt = 0; mt < 2; ++mt)
#pragma unroll
        for (int nf = 0; nf < 8; ++nf)
#pragma unroll
            for (int j = 0; j < 4; ++j) acc[mt][nf][j] = 0.f;

    const int arow = tid >> 2;
    const int akq  = tid & 3;
    const float* aptr = feats + (size_t)(row0 + arow) * NF + akq * 16;
    float insp = 0.f;

    // ldmatrix per-lane base addresses
    const uint32_t aBase = smb + OFF_AH + (uint32_t)(wm * 32 + (lane & 15)) * 144
                         + (uint32_t)(lane >> 4) * 16;
    const uint32_t bBase = smb + OFF_BH + (uint32_t)(lane & 15) * 528
                         + (uint32_t)(wn * 64 + (lane >> 4) * 8) * 2;
    const uint32_t ASTEP = (uint32_t)(OFF_AL - OFF_AH);

    for (int c = 0; c < 4; ++c) {
        __syncthreads();  // smem free (prev compute done / consts visible)

        // ---- A: load fp32, split to fp16 hi/lo, fold inst_pred ----
        {
            const float* ap = aptr + c * 64;
            unsigned char* dstH = sm + OFF_AH + arow * 144 + akq * 32;
            unsigned char* dstL = sm + OFF_AL + arow * 144 + akq * 32;
#pragma unroll
            for (int q = 0; q < 4; ++q) {
                float4 f = *(const float4*)(ap + q * 4);
                const int kk = c * 64 + akq * 16 + q * 4;
                insp += f.x * Wins_s[kk]     + f.y * Wins_s[kk + 1]
                      + f.z * Wins_s[kk + 2] + f.w * Wins_s[kk + 3];
                __half h0 = __float2half_rn(f.x), h1 = __float2half_rn(f.y);
                __half h2 = __float2half_rn(f.z), h3 = __float2half_rn(f.w);
                __half l0 = __float2half_rn(f.x - __half2float(h0));
                __half l1 = __float2half_rn(f.y - __half2float(h1));
                __half l2 = __float2half_rn(f.z - __half2float(h2));
                __half l3 = __float2half_rn(f.w - __half2float(h3));
                *(uint2*)(dstH + q * 8) = make_uint2(pkh(h0, h1), pkh(h2, h3));
                *(uint2*)(dstL + q * 8) = make_uint2(pkh(l0, l1), pkh(l2, l3));
            }
        }
        // ---- B: copy 64k x 256n fp16 from L1/L2-resident g_Wh ----
        {
#pragma unroll
            for (int i = 0; i < 8; ++i) {
                const int idx = tid + 256 * i;
                const int kk = idx >> 5, q = idx & 31;
                const int srcq = ((c * 64 + kk) << 5) + q;
                *(uint4*)(sm + OFF_BH + kk * 528 + q * 16) =
                    __ldg(((const uint4*)g_Wh) + srcq);
            }
        }
        __syncthreads();

        // ---- compute: 2 split terms per k16 step ----
#pragma unroll
        for (int kt = 0; kt < 4; ++kt) {
            const uint32_t aAddr = aBase + kt * 32;
            const uint32_t bAddr = bBase + kt * 16 * 528;
            uint32_t Ah[2][4], Al[2][4], B[4][4];

            ldsm4(Ah[0][0], Ah[0][1], Ah[0][2], Ah[0][3], aAddr);
            ldsm4(Ah[1][0], Ah[1][1], Ah[1][2], Ah[1][3], aAddr + 16 * 144);
#pragma unroll
            for (int n16 = 0; n16 < 4; ++n16)
                ldsm4t(B[n16][0], B[n16][1], B[n16][2], B[n16][3], bAddr + n16 * 32);
#pragma unroll
            for (int mt = 0; mt < 2; ++mt)
#pragma unroll
                for (int nf = 0; nf < 8; ++nf)
                    mma16816(acc[mt][nf], Ah[mt][0], Ah[mt][1], Ah[mt][2], Ah[mt][3],
                             B[nf >> 1][(nf & 1) * 2], B[nf >> 1][(nf & 1) * 2 + 1]);

            ldsm4(Al[0][0], Al[0][1], Al[0][2], Al[0][3], aAddr + ASTEP);
            ldsm4(Al[1][0], Al[1][1], Al[1][2], Al[1][3], aAddr + ASTEP + 16 * 144);
#pragma unroll
            for (int mt = 0; mt < 2; ++mt)
#pragma unroll
                for (int nf = 0; nf < 8; ++nf)
                    mma16816(acc[mt][nf], Al[mt][0], Al[mt][1], Al[mt][2], Al[mt][3],
                             B[nf >> 1][(nf & 1) * 2], B[nf >> 1][(nf & 1) * 2 + 1]);
        }
    }

    // ---- instance predictions ----
    insp += __shfl_xor_sync(0xffffffffu, insp, 1);
    insp += __shfl_xor_sync(0xffffffffu, insp, 2);
    if (akq == 0) out_inst[row0 + arow] = insp + b_ins[0];

    // ---- epilogue: accums -> smem C[64][272], then gated scores ----
    __syncthreads();
    {
        const int rbase = wm * 32 + (lane >> 2);
        const int cbase = wn * 64 + (lane & 3) * 2;
#pragma unroll
        for (int mt = 0; mt < 2; ++mt)
#pragma unroll
            for (int nf = 0; nf < 8; ++nf) {
                float* p0 = (float*)(sm + OFF_C + (rbase + mt * 16) * 1088
                                     + (cbase + nf * 8) * 4);
                p0[0] = acc[mt][nf][0];
                p0[1] = acc[mt][nf][1];
                float* p1 = (float*)(sm + OFF_C + (rbase + mt * 16 + 8) * 1088
                                     + (cbase + nf * 8) * 4);
                p1[0] = acc[mt][nf][2];
                p1[1] = acc[mt][nf][3];
            }
    }
    __syncthreads();
    {
        const float* bV_s = (const float*)(sm + OFF_BV);
        const float* bU_s = (const float*)(sm + OFF_BU);
        const float* wa_s = (const float*)(sm + OFF_WA);
        const unsigned char* crow = sm + OFF_C + arow * 1088;
        float part = 0.f;
#pragma unroll
        for (int jj = 0; jj < 8; ++jj) {
            const int l = jj * 16 + akq * 4;
            float4 v = *(const float4*)(crow + l * 4);
            float4 u = *(const float4*)(crow + (l + L_DIM) * 4);
#pragma unroll
            for (int e = 0; e < 4; ++e) {
                float vv = ((const float*)&v)[e] + bV_s[l + e];
                float uu = ((const float*)&u)[e] + bU_s[l + e];
                float th = 2.f * __fdividef(1.f, 1.f + __expf(-2.f * vv)) - 1.f;
                float sg = __fdividef(1.f, 1.f + __expf(-uu));
                part += th * sg * wa_s[l + e];
            }
        }
        part += __shfl_xor_sync(0xffffffffu, part, 1);
        part += __shfl_xor_sync(0xffffffffu, part, 2);
        if (akq == 0) g_scores[row0 + arow] = part + b_att[0];
    }
}

// ---------------------------------------------------------------------------
// Kernel 2: per-bag segmented softmax + weighted sum (C=1).
// ---------------------------------------------------------------------------
__global__ void bag_kernel(const float* __restrict__ inst,
                           float* __restrict__ out_bag)
{
    const int b   = blockIdx.x;
    const int tid = threadIdx.x;
    const int s0  = g_offs[b];
    const int s1  = g_offs[b + 1];

    __shared__ float rm[4], re[4], rp[4];

    float m = -3.4e38f;
    for (int i = s0 + tid; i < s1; i += 128) m = fmaxf(m, g_scores[i]);
#pragma unroll
    for (int d = 16; d >= 1; d >>= 1)
        m = fmaxf(m, __shfl_xor_sync(0xffffffffu, m, d));
    if ((tid & 31) == 0) rm[tid >> 5] = m;
    __syncthreads();
    m = fmaxf(fmaxf(rm[0], rm[1]), fmaxf(rm[2], rm[3]));

    float se = 0.f, sp = 0.f;
    for (int i = s0 + tid; i < s1; i += 128) {
        float e = expf(g_scores[i] - m);
        se += e;
        sp += e * inst[i];
    }
#pragma unroll
    for (int d = 16; d >= 1; d >>= 1) {
        se += __shfl_xor_sync(0xffffffffu, se, d);
        sp += __shfl_xor_sync(0xffffffffu, sp, d);
    }
    if ((tid & 31) == 0) { re[tid >> 5] = se; rp[tid >> 5] = sp; }
    __syncthreads();
    if (tid == 0) {
        out_bag[b] = (rp[0] + rp[1] + rp[2] + rp[3]) /
                     (re[0] + re[1] + re[2] + re[3]);
    }
}

// ---------------------------------------------------------------------------
extern "C" void kernel_launch(void* const* d_in, const int* in_sizes, int n_in,
                              void* d_out, int out_size)
{
    const float* feats = (const float*)d_in[0];
    const int*   sz32  = (const int*)d_in[1];
    const float* W_ins = (const float*)d_in[2];
    const float* b_ins = (const float*)d_in[3];
    const float* W_V   = (const float*)d_in[4];
    const float* b_V   = (const float*)d_in[5];
    const float* W_U   = (const float*)d_in[6];
    const float* b_U   = (const float*)d_in[7];
    const float* w_att = (const float*)d_in[8];
    const float* b_att = (const float*)d_in[9];

    float* out      = (float*)d_out;
    float* out_bag  = out;           // [4096]
    float* out_inst = out + NBAGS;   // [524288]

    cudaFuncSetAttribute(gemm_kernel, cudaFuncAttributeMaxDynamicSharedMemorySize, SM_TOTAL);

    scan_kernel<<<1, 1024>>>(sz32, W_V, W_U);
    gemm_kernel<<<NTILES, 256, SM_TOTAL>>>(feats, W_ins, b_ins, b_V, b_U,
                                           w_att, b_att, out_inst);
    bag_kernel<<<NBAGS, 128>>>(out_inst, out_bag);
}

// round 7
// speedup vs baseline: 5.8011x; 1.1892x over previous
#include <cuda_runtime.h>
#include <cuda_fp16.h>
#include <math.h>
#include <stdint.h>

// ---------------------------------------------------------------------------
// UnifiedAttentionAggregator — pure fp16 HMMA GEMM (single term)
//   C[N,256] = feats @ [W_V | W_U],  A and W rounded to fp16 (err ~2^-12 each)
// ---------------------------------------------------------------------------

#define N_INST 524288
#define NF     256
#define L_DIM  128
#define NBAGS  4096
#define NTILES (N_INST / 64)

// smem layout (bytes)
#define OFF_WINS 0
#define OFF_BV   1024
#define OFF_BU   1536
#define OFF_WA   2048
#define OFF_AH   2560
#define OFF_BH   (OFF_AH + 64 * 144)       // 11776
#define GEMM_END (OFF_BH + 64 * 528)       // 45568
#define OFF_C    2560                      // epilogue overlay, stride 1088 B
#define SM_TOTAL (OFF_C + 64 * 1088)       // 72192

__device__ float g_scores[N_INST];
__device__ int   g_offs[NBAGS + 1];
__device__ __align__(16) __half g_Wh[NF * 256];  // [k][n] fp16

// ---- helpers --------------------------------------------------------------
__device__ __forceinline__ uint32_t smem_u32(const void* p) {
    uint32_t a;
    asm("{ .reg .u64 t; cvta.to.shared.u64 t, %1; cvt.u32.u64 %0, t; }" : "=r"(a) : "l"(p));
    return a;
}
__device__ __forceinline__ uint32_t cvt_h2(float lo, float hi) {
    uint32_t d;
    asm("cvt.rn.f16x2.f32 %0, %1, %2;" : "=r"(d) : "f"(hi), "f"(lo));
    return d;
}
__device__ __forceinline__ void ldsm4(uint32_t& r0, uint32_t& r1, uint32_t& r2, uint32_t& r3,
                                      uint32_t addr) {
    asm volatile("ldmatrix.sync.aligned.m8n8.x4.shared.b16 {%0,%1,%2,%3}, [%4];"
                 : "=r"(r0), "=r"(r1), "=r"(r2), "=r"(r3) : "r"(addr));
}
__device__ __forceinline__ void ldsm4t(uint32_t& r0, uint32_t& r1, uint32_t& r2, uint32_t& r3,
                                       uint32_t addr) {
    asm volatile("ldmatrix.sync.aligned.m8n8.x4.trans.shared.b16 {%0,%1,%2,%3}, [%4];"
                 : "=r"(r0), "=r"(r1), "=r"(r2), "=r"(r3) : "r"(addr));
}
__device__ __forceinline__ void mma16816(float* c, uint32_t a0, uint32_t a1, uint32_t a2,
                                         uint32_t a3, uint32_t b0, uint32_t b1) {
    asm volatile(
        "mma.sync.aligned.m16n8k16.row.col.f32.f16.f16.f32 "
        "{%0,%1,%2,%3},{%4,%5,%6,%7},{%8,%9},{%0,%1,%2,%3};"
        : "+f"(c[0]), "+f"(c[1]), "+f"(c[2]), "+f"(c[3])
        : "r"(a0), "r"(a1), "r"(a2), "r"(a3), "r"(b0), "r"(b1));
}

// ---------------------------------------------------------------------------
// Kernel 0a: bag-offset scan (1 block)
// ---------------------------------------------------------------------------
__global__ void scan_kernel(const int* __restrict__ sz32) {
    __shared__ int ssum[1024];
    const int t = threadIdx.x;
    const int stride = (sz32[1] == 0) ? 2 : 1;  // int64 storage detection

    int v[4];
    int s = 0;
#pragma unroll
    for (int j = 0; j < 4; ++j) {
        v[j] = sz32[(4 * t + j) * stride];
        s += v[j];
    }
    ssum[t] = s;
    __syncthreads();
    for (int off = 1; off < 1024; off <<= 1) {
        int x = (t >= off) ? ssum[t - off] : 0;
        __syncthreads();
        ssum[t] += x;
        __syncthreads();
    }
    int run = ssum[t] - s;
#pragma unroll
    for (int j = 0; j < 4; ++j) {
        g_offs[4 * t + j] = run;
        run += v[j];
    }
    if (t == 1023) g_offs[NBAGS] = run;
}

// ---------------------------------------------------------------------------
// Kernel 0b: W -> fp16 [k][n] (parallel across 64 blocks)
// ---------------------------------------------------------------------------
__global__ void wsplit_kernel(const float* __restrict__ W_V,
                              const float* __restrict__ W_U) {
    const int idx = blockIdx.x * 1024 + threadIdx.x;
    const int k = idx >> 8, n = idx & 255;
    float w = (n < L_DIM) ? W_V[k * L_DIM + n] : W_U[k * L_DIM + (n - L_DIM)];
    g_Wh[idx] = __float2half_rn(w);
}

// ---------------------------------------------------------------------------
// Kernel 1: HMMA GEMM + inst_pred + gated-attention epilogue.
// Block: 256 thr (8 warps 2x4), tile 64x256, K chunks of 64, 2 CTAs/SM.
// ---------------------------------------------------------------------------
__global__ __launch_bounds__(256, 2) void gemm_kernel(
    const float* __restrict__ feats,
    const float* __restrict__ W_ins, const float* __restrict__ b_ins,
    const float* __restrict__ b_V, const float* __restrict__ b_U,
    const float* __restrict__ w_att, const float* __restrict__ b_att,
    float* __restrict__ out_inst)
{
    extern __shared__ __align__(16) unsigned char sm[];
    const int tid  = threadIdx.x;
    const int wid  = tid >> 5;
    const int lane = tid & 31;
    const int wm   = wid & 1;    // M-warp (32 rows)
    const int wn   = wid >> 1;   // N-warp (64 cols)
    const int row0 = blockIdx.x * 64;
    const uint32_t smb = smem_u32(sm);

    // consts
    ((float*)(sm + OFF_WINS))[tid] = W_ins[tid];
    if (tid < L_DIM) {
        ((float*)(sm + OFF_BV))[tid] = b_V[tid];
        ((float*)(sm + OFF_BU))[tid] = b_U[tid];
        ((float*)(sm + OFF_WA))[tid] = w_att[tid];
    }
    const float* Wins_s = (const float*)(sm + OFF_WINS);

    float acc[2][8][4];
#pragma unroll
    for (int mt = 0; mt < 2; ++mt)
#pragma unroll
        for (int nf = 0; nf < 8; ++nf)
#pragma unroll
            for (int j = 0; j < 4; ++j) acc[mt][nf][j] = 0.f;

    const int arow = tid >> 2;
    const int akq  = tid & 3;
    const float* aptr = feats + (size_t)(row0 + arow) * NF + akq * 16;
    float insp = 0.f;

    // ldmatrix per-lane base addresses
    const uint32_t aBase = smb + OFF_AH + (uint32_t)(wm * 32 + (lane & 15)) * 144
                         + (uint32_t)(lane >> 4) * 16;
    const uint32_t bBase = smb + OFF_BH + (uint32_t)(lane & 15) * 528
                         + (uint32_t)(wn * 64 + (lane >> 4) * 8) * 2;

    for (int c = 0; c < 4; ++c) {
        __syncthreads();  // smem free (prev compute done / consts visible)

        // ---- A: load fp32, convert fp16, fold inst_pred ----
        {
            const float* ap = aptr + c * 64;
            unsigned char* dstH = sm + OFF_AH + arow * 144 + akq * 32;
#pragma unroll
            for (int q = 0; q < 4; ++q) {
                float4 f = *(const float4*)(ap + q * 4);
                const int kk = c * 64 + akq * 16 + q * 4;
                insp += f.x * Wins_s[kk]     + f.y * Wins_s[kk + 1]
                      + f.z * Wins_s[kk + 2] + f.w * Wins_s[kk + 3];
                *(uint2*)(dstH + q * 8) =
                    make_uint2(cvt_h2(f.x, f.y), cvt_h2(f.z, f.w));
            }
        }
        // ---- B: copy 64k x 256n fp16 from L1/L2-resident g_Wh ----
        {
#pragma unroll
            for (int i = 0; i < 8; ++i) {
                const int idx = tid + 256 * i;
                const int kk = idx >> 5, q = idx & 31;
                const int srcq = ((c * 64 + kk) << 5) + q;
                *(uint4*)(sm + OFF_BH + kk * 528 + q * 16) =
                    __ldg(((const uint4*)g_Wh) + srcq);
            }
        }
        __syncthreads();

        // ---- compute ----
#pragma unroll
        for (int kt = 0; kt < 4; ++kt) {
            const uint32_t aAddr = aBase + kt * 32;
            const uint32_t bAddr = bBase + kt * 16 * 528;
            uint32_t Ah[2][4], B[4][4];

            ldsm4(Ah[0][0], Ah[0][1], Ah[0][2], Ah[0][3], aAddr);
            ldsm4(Ah[1][0], Ah[1][1], Ah[1][2], Ah[1][3], aAddr + 16 * 144);
#pragma unroll
            for (int n16 = 0; n16 < 4; ++n16)
                ldsm4t(B[n16][0], B[n16][1], B[n16][2], B[n16][3], bAddr + n16 * 32);
#pragma unroll
            for (int mt = 0; mt < 2; ++mt)
#pragma unroll
                for (int nf = 0; nf < 8; ++nf)
                    mma16816(acc[mt][nf], Ah[mt][0], Ah[mt][1], Ah[mt][2], Ah[mt][3],
                             B[nf >> 1][(nf & 1) * 2], B[nf >> 1][(nf & 1) * 2 + 1]);
        }
    }

    // ---- instance predictions ----
    insp += __shfl_xor_sync(0xffffffffu, insp, 1);
    insp += __shfl_xor_sync(0xffffffffu, insp, 2);
    if (akq == 0) out_inst[row0 + arow] = insp + b_ins[0];

    // ---- epilogue: accums -> smem C[64][272], then gated scores ----
    __syncthreads();
    {
        const int rbase = wm * 32 + (lane >> 2);
        const int cbase = wn * 64 + (lane & 3) * 2;
#pragma unroll
        for (int mt = 0; mt < 2; ++mt)
#pragma unroll
            for (int nf = 0; nf < 8; ++nf) {
                float* p0 = (float*)(sm + OFF_C + (rbase + mt * 16) * 1088
                                     + (cbase + nf * 8) * 4);
                p0[0] = acc[mt][nf][0];
                p0[1] = acc[mt][nf][1];
                float* p1 = (float*)(sm + OFF_C + (rbase + mt * 16 + 8) * 1088
                                     + (cbase + nf * 8) * 4);
                p1[0] = acc[mt][nf][2];
                p1[1] = acc[mt][nf][3];
            }
    }
    __syncthreads();
    {
        const float* bV_s = (const float*)(sm + OFF_BV);
        const float* bU_s = (const float*)(sm + OFF_BU);
        const float* wa_s = (const float*)(sm + OFF_WA);
        const unsigned char* crow = sm + OFF_C + arow * 1088;
        float part = 0.f;
#pragma unroll
        for (int jj = 0; jj < 8; ++jj) {
            const int l = jj * 16 + akq * 4;
            float4 v = *(const float4*)(crow + l * 4);
            float4 u = *(const float4*)(crow + (l + L_DIM) * 4);
#pragma unroll
            for (int e = 0; e < 4; ++e) {
                float vv = ((const float*)&v)[e] + bV_s[l + e];
                float uu = ((const float*)&u)[e] + bU_s[l + e];
                float th = 2.f * __fdividef(1.f, 1.f + __expf(-2.f * vv)) - 1.f;
                float sg = __fdividef(1.f, 1.f + __expf(-uu));
                part += th * sg * wa_s[l + e];
            }
        }
        part += __shfl_xor_sync(0xffffffffu, part, 1);
        part += __shfl_xor_sync(0xffffffffu, part, 2);
        if (akq == 0) g_scores[row0 + arow] = part + b_att[0];
    }
}

// ---------------------------------------------------------------------------
// Kernel 2: per-bag segmented softmax + weighted sum (C=1).
// ---------------------------------------------------------------------------
__global__ void bag_kernel(const float* __restrict__ inst,
                           float* __restrict__ out_bag)
{
    const int b   = blockIdx.x;
    const int tid = threadIdx.x;
    const int s0  = g_offs[b];
    const int s1  = g_offs[b + 1];

    __shared__ float rm[4], re[4], rp[4];

    float m = -3.4e38f;
    for (int i = s0 + tid; i < s1; i += 128) m = fmaxf(m, g_scores[i]);
#pragma unroll
    for (int d = 16; d >= 1; d >>= 1)
        m = fmaxf(m, __shfl_xor_sync(0xffffffffu, m, d));
    if ((tid & 31) == 0) rm[tid >> 5] = m;
    __syncthreads();
    m = fmaxf(fmaxf(rm[0], rm[1]), fmaxf(rm[2], rm[3]));

    float se = 0.f, sp = 0.f;
    for (int i = s0 + tid; i < s1; i += 128) {
        float e = expf(g_scores[i] - m);
        se += e;
        sp += e * inst[i];
    }
#pragma unroll
    for (int d = 16; d >= 1; d >>= 1) {
        se += __shfl_xor_sync(0xffffffffu, se, d);
        sp += __shfl_xor_sync(0xffffffffu, sp, d);
    }
    if ((tid & 31) == 0) { re[tid >> 5] = se; rp[tid >> 5] = sp; }
    __syncthreads();
    if (tid == 0) {
        out_bag[b] = (rp[0] + rp[1] + rp[2] + rp[3]) /
                     (re[0] + re[1] + re[2] + re[3]);
    }
}

// ---------------------------------------------------------------------------
extern "C" void kernel_launch(void* const* d_in, const int* in_sizes, int n_in,
                              void* d_out, int out_size)
{
    const float* feats = (const float*)d_in[0];
    const int*   sz32  = (const int*)d_in[1];
    const float* W_ins = (const float*)d_in[2];
    const float* b_ins = (const float*)d_in[3];
    const float* W_V   = (const float*)d_in[4];
    const float* b_V   = (const float*)d_in[5];
    const float* W_U   = (const float*)d_in[6];
    const float* b_U   = (const float*)d_in[7];
    const float* w_att = (const float*)d_in[8];
    const float* b_att = (const float*)d_in[9];

    float* out      = (float*)d_out;
    float* out_bag  = out;           // [4096]
    float* out_inst = out + NBAGS;   // [524288]

    cudaFuncSetAttribute(gemm_kernel, cudaFuncAttributeMaxDynamicSharedMemorySize, SM_TOTAL);

    scan_kernel<<<1, 1024>>>(sz32);
    wsplit_kernel<<<64, 1024>>>(W_V, W_U);
    gemm_kernel<<<NTILES, 256, SM_TOTAL>>>(feats, W_ins, b_ins, b_V, b_U,
                                           w_att, b_att, out_inst);
    bag_kernel<<<NBAGS, 128>>>(out_inst, out_bag);
}

// round 8
// speedup vs baseline: 6.9614x; 1.2000x over previous
#include <cuda_runtime.h>
#include <cuda_fp16.h>
#include <math.h>
#include <stdint.h>

// ---------------------------------------------------------------------------
// UnifiedAttentionAggregator — fp16 HMMA GEMM, W smem-resident, A pipelined
//   C[N,256] = feats @ [W_V | W_U]
// ---------------------------------------------------------------------------

#define N_INST 524288
#define NF     256
#define L_DIM  128
#define NBAGS  4096
#define NTILES (N_INST / 128)

// smem layout (bytes)
#define OFF_WINS 0
#define OFF_BV   1024
#define OFF_BU   1536
#define OFF_WA   2048
#define OFF_AH   2560
#define A_BUF    18432                      // 128 rows * 144 B
#define OFF_B    (OFF_AH + 2 * A_BUF)       // 39424
#define SM_TOTAL (OFF_B + 256 * 528)        // 174592
#define OFF_C    2560                       // epilogue overlay, stride 1088 B

__device__ float g_scores[N_INST];
__device__ int   g_offs[NBAGS + 1];
__device__ __align__(16) __half g_Wh[NF * 256];  // [k][n] fp16

// ---- helpers --------------------------------------------------------------
__device__ __forceinline__ uint32_t smem_u32(const void* p) {
    uint32_t a;
    asm("{ .reg .u64 t; cvta.to.shared.u64 t, %1; cvt.u32.u64 %0, t; }" : "=r"(a) : "l"(p));
    return a;
}
__device__ __forceinline__ uint32_t cvt_h2(float lo, float hi) {
    uint32_t d;
    asm("cvt.rn.f16x2.f32 %0, %1, %2;" : "=r"(d) : "f"(hi), "f"(lo));
    return d;
}
__device__ __forceinline__ void ldsm4(uint32_t& r0, uint32_t& r1, uint32_t& r2, uint32_t& r3,
                                      uint32_t addr) {
    asm volatile("ldmatrix.sync.aligned.m8n8.x4.shared.b16 {%0,%1,%2,%3}, [%4];"
                 : "=r"(r0), "=r"(r1), "=r"(r2), "=r"(r3) : "r"(addr));
}
__device__ __forceinline__ void ldsm4t(uint32_t& r0, uint32_t& r1, uint32_t& r2, uint32_t& r3,
                                       uint32_t addr) {
    asm volatile("ldmatrix.sync.aligned.m8n8.x4.trans.shared.b16 {%0,%1,%2,%3}, [%4];"
                 : "=r"(r0), "=r"(r1), "=r"(r2), "=r"(r3) : "r"(addr));
}
__device__ __forceinline__ void mma16816(float* c, uint32_t a0, uint32_t a1, uint32_t a2,
                                         uint32_t a3, uint32_t b0, uint32_t b1) {
    asm volatile(
        "mma.sync.aligned.m16n8k16.row.col.f32.f16.f16.f32 "
        "{%0,%1,%2,%3},{%4,%5,%6,%7},{%8,%9},{%0,%1,%2,%3};"
        : "+f"(c[0]), "+f"(c[1]), "+f"(c[2]), "+f"(c[3])
        : "r"(a0), "r"(a1), "r"(a2), "r"(a3), "r"(b0), "r"(b1));
}

// ---------------------------------------------------------------------------
// Kernel 0a: bag-offset scan, shfl-based (2 syncs)
// ---------------------------------------------------------------------------
__global__ void scan_kernel(const int* __restrict__ sz32) {
    __shared__ int wsum[32];
    const int t = threadIdx.x, lane = t & 31, w = t >> 5;
    const int stride = (sz32[1] == 0) ? 2 : 1;  // int64 storage detection

    int v[4];
    int s = 0;
#pragma unroll
    for (int j = 0; j < 4; ++j) {
        v[j] = sz32[(4 * t + j) * stride];
        s += v[j];
    }
    const int own = s;
#pragma unroll
    for (int d = 1; d < 32; d <<= 1) {
        int x = __shfl_up_sync(0xffffffffu, s, d);
        if (lane >= d) s += x;
    }
    if (lane == 31) wsum[w] = s;
    __syncthreads();
    if (w == 0) {
        int x = wsum[lane];
#pragma unroll
        for (int d = 1; d < 32; d <<= 1) {
            int y = __shfl_up_sync(0xffffffffu, x, d);
            if (lane >= d) x += y;
        }
        wsum[lane] = x;
    }
    __syncthreads();
    int run = (w ? wsum[w - 1] : 0) + s - own;  // exclusive prefix
#pragma unroll
    for (int j = 0; j < 4; ++j) {
        g_offs[4 * t + j] = run;
        run += v[j];
    }
    if (t == 1023) g_offs[NBAGS] = run;
}

// ---------------------------------------------------------------------------
// Kernel 0b: W -> fp16 [k][n]
// ---------------------------------------------------------------------------
__global__ void wsplit_kernel(const float* __restrict__ W_V,
                              const float* __restrict__ W_U) {
    const int idx = blockIdx.x * 1024 + threadIdx.x;
    const int k = idx >> 8, n = idx & 255;
    float w = (n < L_DIM) ? W_V[k * L_DIM + n] : W_U[k * L_DIM + (n - L_DIM)];
    g_Wh[idx] = __float2half_rn(w);
}

// ---------------------------------------------------------------------------
// Kernel 1: HMMA GEMM, B resident in smem, A double-buffered.
// Block: 512 thr (16 warps 4x4), tile 128x256, K chunks of 64, 1 CTA/SM.
// ---------------------------------------------------------------------------
__global__ __launch_bounds__(512, 1) void gemm_kernel(
    const float* __restrict__ feats,
    const float* __restrict__ W_ins, const float* __restrict__ b_ins,
    const float* __restrict__ b_V, const float* __restrict__ b_U,
    const float* __restrict__ w_att, const float* __restrict__ b_att,
    float* __restrict__ out_inst)
{
    extern __shared__ __align__(16) unsigned char sm[];
    const int tid  = threadIdx.x;
    const int wid  = tid >> 5;
    const int lane = tid & 31;
    const int wm   = wid & 3;    // M-warp (32 rows)
    const int wn   = wid >> 2;   // N-warp (64 cols)
    const int row0 = blockIdx.x * 128;
    const uint32_t smb = smem_u32(sm);

    // consts
    if (tid < 256) ((float*)(sm + OFF_WINS))[tid] = W_ins[tid];
    if (tid < L_DIM) {
        ((float*)(sm + OFF_BV))[tid] = b_V[tid];
        ((float*)(sm + OFF_BU))[tid] = b_U[tid];
        ((float*)(sm + OFF_WA))[tid] = w_att[tid];
    }
    // B: full 256x256 fp16 W into smem, once
#pragma unroll
    for (int i = 0; i < 16; ++i) {
        const int idx = tid + 512 * i;          // 8192 uint4
        const int kk = idx >> 5, q = idx & 31;
        *(uint4*)(sm + OFF_B + kk * 528 + q * 16) = __ldg(((const uint4*)g_Wh) + idx);
    }
    const float* Wins_s = (const float*)(sm + OFF_WINS);

    float acc[2][8][4];
#pragma unroll
    for (int mt = 0; mt < 2; ++mt)
#pragma unroll
        for (int nf = 0; nf < 8; ++nf)
#pragma unroll
            for (int j = 0; j < 4; ++j) acc[mt][nf][j] = 0.f;

    const int arow = tid >> 2;
    const int akq  = tid & 3;
    const float* aptr = feats + (size_t)(row0 + arow) * NF + akq * 16;
    unsigned char* aDst = sm + OFF_AH + arow * 144 + akq * 32;
    float insp = 0.f;

    const uint32_t aBase = smb + OFF_AH + (uint32_t)(wm * 32 + (lane & 15)) * 144
                         + (uint32_t)(lane >> 4) * 16;
    const uint32_t bBase = smb + OFF_B + (uint32_t)(lane & 15) * 528
                         + (uint32_t)(wn * 64 + (lane >> 4) * 8) * 2;

    // prologue: chunk 0 -> buf 0
    float4 f[4];
#pragma unroll
    for (int q = 0; q < 4; ++q) f[q] = *(const float4*)(aptr + q * 4);
#pragma unroll
    for (int q = 0; q < 4; ++q) {
        const int kk = akq * 16 + q * 4;
        insp += f[q].x * Wins_s[kk]     + f[q].y * Wins_s[kk + 1]
              + f[q].z * Wins_s[kk + 2] + f[q].w * Wins_s[kk + 3];
        *(uint2*)(aDst + q * 8) = make_uint2(cvt_h2(f[q].x, f[q].y), cvt_h2(f[q].z, f[q].w));
    }
    __syncthreads();

    for (int c = 0; c < 4; ++c) {
        // prefetch next A chunk into registers (hidden under compute)
        if (c < 3) {
            const float* ap = aptr + (c + 1) * 64;
#pragma unroll
            for (int q = 0; q < 4; ++q) f[q] = *(const float4*)(ap + q * 4);
        }

        // ---- compute chunk c from buf[c&1] ----
        const uint32_t aBufc = aBase + (uint32_t)(c & 1) * A_BUF;
#pragma unroll
        for (int kt = 0; kt < 4; ++kt) {
            const uint32_t aAddr = aBufc + kt * 32;
            const uint32_t bAddr = bBase + (uint32_t)(c * 64 + kt * 16) * 528;
            uint32_t Ah[2][4], B[4][4];

            ldsm4(Ah[0][0], Ah[0][1], Ah[0][2], Ah[0][3], aAddr);
            ldsm4(Ah[1][0], Ah[1][1], Ah[1][2], Ah[1][3], aAddr + 16 * 144);
#pragma unroll
            for (int n16 = 0; n16 < 4; ++n16)
                ldsm4t(B[n16][0], B[n16][1], B[n16][2], B[n16][3], bAddr + n16 * 32);
#pragma unroll
            for (int mt = 0; mt < 2; ++mt)
#pragma unroll
                for (int nf = 0; nf < 8; ++nf)
                    mma16816(acc[mt][nf], Ah[mt][0], Ah[mt][1], Ah[mt][2], Ah[mt][3],
                             B[nf >> 1][(nf & 1) * 2], B[nf >> 1][(nf & 1) * 2 + 1]);
        }

        // ---- convert+store next chunk to buf[(c+1)&1] ----
        if (c < 3) {
            unsigned char* dst = aDst + ((c + 1) & 1) * A_BUF;
#pragma unroll
            for (int q = 0; q < 4; ++q) {
                const int kk = (c + 1) * 64 + akq * 16 + q * 4;
                insp += f[q].x * Wins_s[kk]     + f[q].y * Wins_s[kk + 1]
                      + f[q].z * Wins_s[kk + 2] + f[q].w * Wins_s[kk + 3];
                *(uint2*)(dst + q * 8) =
                    make_uint2(cvt_h2(f[q].x, f[q].y), cvt_h2(f[q].z, f[q].w));
            }
            __syncthreads();
        }
    }

    // ---- instance predictions ----
    insp += __shfl_xor_sync(0xffffffffu, insp, 1);
    insp += __shfl_xor_sync(0xffffffffu, insp, 2);
    if (akq == 0) out_inst[row0 + arow] = insp + b_ins[0];

    // ---- epilogue: accums -> smem C[128][272] (overlays A+B), gated scores
    __syncthreads();
    {
        const int rbase = wm * 32 + (lane >> 2);
        const int cbase = wn * 64 + (lane & 3) * 2;
#pragma unroll
        for (int mt = 0; mt < 2; ++mt)
#pragma unroll
            for (int nf = 0; nf < 8; ++nf) {
                float* p0 = (float*)(sm + OFF_C + (rbase + mt * 16) * 1088
                                     + (cbase + nf * 8) * 4);
                p0[0] = acc[mt][nf][0];
                p0[1] = acc[mt][nf][1];
                float* p1 = (float*)(sm + OFF_C + (rbase + mt * 16 + 8) * 1088
                                     + (cbase + nf * 8) * 4);
                p1[0] = acc[mt][nf][2];
                p1[1] = acc[mt][nf][3];
            }
    }
    __syncthreads();
    {
        const float* bV_s = (const float*)(sm + OFF_BV);
        const float* bU_s = (const float*)(sm + OFF_BU);
        const float* wa_s = (const float*)(sm + OFF_WA);
        const unsigned char* crow = sm + OFF_C + arow * 1088;
        float part = 0.f;
#pragma unroll
        for (int jj = 0; jj < 8; ++jj) {
            const int l = jj * 16 + akq * 4;
            float4 v = *(const float4*)(crow + l * 4);
            float4 u = *(const float4*)(crow + (l + L_DIM) * 4);
#pragma unroll
            for (int e = 0; e < 4; ++e) {
                float vv = ((const float*)&v)[e] + bV_s[l + e];
                float uu = ((const float*)&u)[e] + bU_s[l + e];
                float th = 2.f * __fdividef(1.f, 1.f + __expf(-2.f * vv)) - 1.f;
                float sg = __fdividef(1.f, 1.f + __expf(-uu));
                part += th * sg * wa_s[l + e];
            }
        }
        part += __shfl_xor_sync(0xffffffffu, part, 1);
        part += __shfl_xor_sync(0xffffffffu, part, 2);
        if (akq == 0) g_scores[row0 + arow] = part + b_att[0];
    }
}

// ---------------------------------------------------------------------------
// Kernel 2: per-bag segmented softmax + weighted sum (C=1).
// ---------------------------------------------------------------------------
__global__ void bag_kernel(const float* __restrict__ inst,
                           float* __restrict__ out_bag)
{
    const int b   = blockIdx.x;
    const int tid = threadIdx.x;
    const int s0  = g_offs[b];
    const int s1  = g_offs[b + 1];

    __shared__ float rm[4], re[4], rp[4];

    float m = -3.4e38f;
    for (int i = s0 + tid; i < s1; i += 128) m = fmaxf(m, g_scores[i]);
#pragma unroll
    for (int d = 16; d >= 1; d >>= 1)
        m = fmaxf(m, __shfl_xor_sync(0xffffffffu, m, d));
    if ((tid & 31) == 0) rm[tid >> 5] = m;
    __syncthreads();
    m = fmaxf(fmaxf(rm[0], rm[1]), fmaxf(rm[2], rm[3]));

    float se = 0.f, sp = 0.f;
    for (int i = s0 + tid; i < s1; i += 128) {
        float e = expf(g_scores[i] - m);
        se += e;
        sp += e * inst[i];
    }
#pragma unroll
    for (int d = 16; d >= 1; d >>= 1) {
        se += __shfl_xor_sync(0xffffffffu, se, d);
        sp += __shfl_xor_sync(0xffffffffu, sp, d);
    }
    if ((tid & 31) == 0) { re[tid >> 5] = se; rp[tid >> 5] = sp; }
    __syncthreads();
    if (tid == 0) {
        out_bag[b] = (rp[0] + rp[1] + rp[2] + rp[3]) /
                     (re[0] + re[1] + re[2] + re[3]);
    }
}

// ---------------------------------------------------------------------------
extern "C" void kernel_launch(void* const* d_in, const int* in_sizes, int n_in,
                              void* d_out, int out_size)
{
    const float* feats = (const float*)d_in[0];
    const int*   sz32  = (const int*)d_in[1];
    const float* W_ins = (const float*)d_in[2];
    const float* b_ins = (const float*)d_in[3];
    const float* W_V   = (const float*)d_in[4];
    const float* b_V   = (const float*)d_in[5];
    const float* W_U   = (const float*)d_in[6];
    const float* b_U   = (const float*)d_in[7];
    const float* w_att = (const float*)d_in[8];
    const float* b_att = (const float*)d_in[9];

    float* out      = (float*)d_out;
    float* out_bag  = out;           // [4096]
    float* out_inst = out + NBAGS;   // [524288]

    cudaFuncSetAttribute(gemm_kernel, cudaFuncAttributeMaxDynamicSharedMemorySize, SM_TOTAL);

    scan_kernel<<<1, 1024>>>(sz32);
    wsplit_kernel<<<64, 1024>>>(W_V, W_U);
    gemm_kernel<<<NTILES, 512, SM_TOTAL>>>(feats, W_ins, b_ins, b_V, b_U,
                                           w_att, b_att, out_inst);
    bag_kernel<<<NBAGS, 128>>>(out_inst, out_bag);
}